// round 9
// baseline (speedup 1.0000x reference)
#include <cuda_runtime.h>
#include <math.h>

// ---------------------------------------------------------------------------
// maps[b] = bilin_up(out0,64)+bilin_up(out1,32)+bilin_up(out2,16) -> 256x256
// scores[b] = max( reflect-pad 5x5 gaussian blur of maps[b] )
// d_out = [256 scores][256*256*256 maps] fp32.
//
// 2048 blocks = (batch, 32-row strip), 64 threads = 2 warps; thread owns 4
// columns (2 packed f32x2 pairs); warp covers 128 cols, block covers the row.
// m stays in registers; h-blur neighbors via warp shuffles; only the
// warp0/warp1 seam goes through smem (parity double-buffered, 1 sync/row).
// Incremental bilinear (float fy wrap; brackets recomputed only in the rare
// uniform wrap branch), register-ring v-blur, STG.128 maps store.
// Fused per-batch max via encoded atomicMax + arrival counter (8 blocks/batch).
// ---------------------------------------------------------------------------

typedef unsigned long long ull;

#define W0 0.18762723f
#define W1 0.20606817f
#define W2 0.21260941f

__device__ __forceinline__ ull pk2(float a, float b) {
    ull r; asm("mov.b64 %0, {%1,%2};" : "=l"(r) : "f"(a), "f"(b)); return r;
}
__device__ __forceinline__ float2 up2(ull v) {
    float2 r; asm("mov.b64 {%0,%1}, %2;" : "=f"(r.x), "=f"(r.y) : "l"(v)); return r;
}
__device__ __forceinline__ ull f2add(ull a, ull b) {
    ull r; asm("add.rn.f32x2 %0,%1,%2;" : "=l"(r) : "l"(a), "l"(b)); return r;
}
__device__ __forceinline__ ull f2mul(ull a, ull b) {
    ull r; asm("mul.rn.f32x2 %0,%1,%2;" : "=l"(r) : "l"(a), "l"(b)); return r;
}
__device__ __forceinline__ ull f2fma(ull a, ull b, ull c) {
    ull r; asm("fma.rn.f32x2 %0,%1,%2,%3;" : "=l"(r) : "l"(a), "l"(b), "l"(c)); return r;
}

__device__ __forceinline__ unsigned enc_f(float f) {
    unsigned u = __float_as_uint(f);
    return (u & 0x80000000u) ? ~u : (u | 0x80000000u);
}
__device__ __forceinline__ float dec_f(unsigned u) {
    return (u & 0x80000000u) ? __uint_as_float(u & 0x7fffffffu)
                             : __uint_as_float(~u);
}

__device__ unsigned g_enc[256];   // zero-init; reset by last block each call
__device__ unsigned g_cnt[256];   // zero-init; reset by last block each call

// x-lerp of a column pair (c, c+1) from a staged source row
template<int H>
__device__ __forceinline__ float2 xl2c(const float* row, int c) {
    int n0 = c * (H - 1), n1 = n0 + (H - 1);
    int x0 = n0 / 255, x1 = n1 / 255;
    float f0 = (float)(n0 - 255 * x0) * (1.0f / 255.0f);
    float f1 = (float)(n1 - 255 * x1) * (1.0f / 255.0f);
    float A = row[x0], B = row[min(x0 + 1, H - 1)];
    float C = row[x1], D = row[min(x1 + 1, H - 1)];
    return make_float2(fmaf(f0, B - A, A), fmaf(f1, D - C, C));
}

template<int H>
struct S2 {
    float fy;
    int   ro;                   // smem offset of source row y0
    ull   xlA, xdA, xlB, xdB;   // packed x-lerp at y0 and (hi-lo), 2 pairs
};

template<int H>
__device__ __forceinline__ void s2_init(S2<H>& s, const float* sm, int y, int rlo, int cb) {
    int num = y * (H - 1);
    int y0 = num / 255;
    s.fy = (float)(num - 255 * y0) * (1.0f / 255.0f);
    s.ro = (y0 - rlo) * H;
    float2 loA = xl2c<H>(sm + s.ro, cb);
    float2 hiA = xl2c<H>(sm + s.ro + H, cb);      // guard row keeps this defined
    float2 loB = xl2c<H>(sm + s.ro, cb + 2);
    float2 hiB = xl2c<H>(sm + s.ro + H, cb + 2);
    s.xlA = pk2(loA.x, loA.y); s.xdA = pk2(hiA.x - loA.x, hiA.y - loA.y);
    s.xlB = pk2(loB.x, loB.y); s.xdB = pk2(hiB.x - loB.x, hiB.y - loB.y);
}

template<int H>
__device__ __forceinline__ void s2_adv(S2<H>& s, const float* sm, int cb) {
    s.fy += (float)(H - 1) * (1.0f / 255.0f);     // FADD immediate
    if (s.fy >= 1.0f) {                            // uniform, rarely taken
        s.fy -= 1.0f;
        s.ro += H;
        s.xlA = f2add(s.xlA, s.xdA);               // new lo = old hi
        s.xlB = f2add(s.xlB, s.xdB);
        float2 hiA = xl2c<H>(sm + s.ro + H, cb);
        float2 hiB = xl2c<H>(sm + s.ro + H, cb + 2);
        float2 loA = up2(s.xlA), loB = up2(s.xlB);
        s.xdA = pk2(hiA.x - loA.x, hiA.y - loA.y);
        s.xdB = pk2(hiB.x - loB.x, hiB.y - loB.y);
    }
}

// One output row: bilinear m (2 pairs), seam exchange, shuffle h-blur,
// optional maps store and v-blur/max, ring shift, optional state advance.
#define DO_ROW(PAR, DOSTG, DOV, DOADV)                                         \
{                                                                              \
    ull fp0 = pk2(sA.fy, sA.fy);                                               \
    ull fp1 = pk2(sB.fy, sB.fy);                                               \
    ull fp2 = pk2(sC.fy, sC.fy);                                               \
    ull mA2 = f2add(f2add(f2fma(fp0, sA.xdA, sA.xlA),                          \
                          f2fma(fp1, sB.xdA, sB.xlA)),                         \
                    f2fma(fp2, sC.xdA, sC.xlA));                               \
    ull mB2 = f2add(f2add(f2fma(fp0, sA.xdB, sA.xlB),                          \
                          f2fma(fp1, sB.xdB, sB.xlB)),                         \
                    f2fma(fp2, sC.xdB, sC.xlB));                               \
    if (DOSTG) {                                                               \
        longlong2 stv; stv.x = (long long)mA2; stv.y = (long long)mB2;         \
        *(longlong2*)mp = stv; mp += 256;                                      \
    }                                                                          \
    if (tid == 31) bndW0[PAR] = mB2;                                           \
    if (tid == 32) bndW1[PAR] = mA2;                                           \
    __syncthreads();                                                           \
    float2 av = up2(mA2), bv = up2(mB2);                                       \
    float prx = __shfl_up_sync(0xffffffffu, bv.x, 1);                          \
    float pry = __shfl_up_sync(0xffffffffu, bv.y, 1);                          \
    float nxx = __shfl_down_sync(0xffffffffu, av.x, 1);                        \
    float nxy = __shfl_down_sync(0xffffffffu, av.y, 1);                        \
    ull bo = bnd_other[PAR];                                                   \
    float2 bof = up2(bo);                                                      \
    if (lane == 0)  { prx = isW0 ? bv.x : bof.x; pry = isW0 ? av.y : bof.y; }  \
    if (lane == 31) { nxx = isW0 ? bof.x : bv.x; nxy = isW0 ? bof.y : av.y; }  \
    ull t0 = pk2(prx, pry);                                                    \
    ull t1 = pk2(pry, av.x);                                                   \
    ull t3 = pk2(av.y, bv.x);                                                  \
    ull heA = f2fma(w0p, f2add(t0, mB2),                                       \
              f2fma(w1p, f2add(t1, t3), f2mul(w2p, mA2)));                     \
    ull t3b = pk2(bv.y, nxx);                                                  \
    ull t4b = pk2(nxx, nxy);                                                   \
    ull heB = f2fma(w0p, f2add(mA2, t4b),                                      \
              f2fma(w1p, f2add(t3, t3b), f2mul(w2p, mB2)));                    \
    if (DOV) {                                                                 \
        ull vA = f2fma(w0p, f2add(haA, heA),                                   \
                 f2fma(w1p, f2add(hbA, hdA), f2mul(w2p, hcA)));                \
        ull vB = f2fma(w0p, f2add(haB, heB),                                   \
                 f2fma(w1p, f2add(hbB, hdB), f2mul(w2p, hcB)));                \
        float2 va = up2(vA), vb = up2(vB);                                     \
        lmax = fmaxf(lmax, fmaxf(fmaxf(va.x, va.y), fmaxf(vb.x, vb.y)));       \
    }                                                                          \
    haA = hbA; hbA = hcA; hcA = hdA; hdA = heA;                                \
    haB = hbB; hbB = hcB; hcB = hdB; hdB = heB;                                \
    if (DOADV) {                                                               \
        s2_adv(sA, s0, cb); s2_adv(sB, s1, cb); s2_adv(sC, s2, cb);            \
    }                                                                          \
}

__global__ void __launch_bounds__(64, 10)
fused_strip(const float* __restrict__ in0,
            const float* __restrict__ in1,
            const float* __restrict__ in2,
            float* __restrict__ maps,
            float* __restrict__ scores) {
    __shared__ __align__(16) float s0[12 * 64];   // staged + guard row
    __shared__ __align__(16) float s1[8 * 32];
    __shared__ __align__(16) float s2[6 * 16];
    __shared__ ull bndW0[2], bndW1[2];            // seam pairs, parity buffered
    __shared__ float wred[2];

    const int tid = threadIdx.x;
    const int lane = tid & 31;
    const bool isW0 = tid < 32;
    const int bx = blockIdx.x;
    const int b  = bx >> 3;
    const int q  = bx & 7;
    const int Y0 = q << 5;
    const int cb = (tid >> 5) * 128 + lane * 4;   // this thread's 4 columns

    const int amin = max(0, Y0 - 2);
    const int amax = min(255, Y0 + 33);
    const int rlo0 = (amin * 63) / 255;
    const int rlo1 = (amin * 31) / 255;
    const int rlo2 = (amin * 15) / 255;
    const int rhi0 = min((amax * 63) / 255 + 1, 63);
    const int rhi1 = min((amax * 31) / 255 + 1, 31);
    const int rhi2 = min((amax * 15) / 255 + 1, 15);

    // stage sources (coalesced float4) + guard row (duplicate of last row)
    {
        const float* gb = in0 + (size_t)b * 4096 + rlo0 * 64;
        int n = (rhi0 - rlo0 + 1) * 16;
        for (int i = tid; i < n; i += 64) ((float4*)s0)[i] = ((const float4*)gb)[i];
        const float* gr = in0 + (size_t)b * 4096 + rhi0 * 64;
        s0[n * 4 + tid] = gr[tid];
    }
    {
        const float* gb = in1 + (size_t)b * 1024 + rlo1 * 32;
        int n = (rhi1 - rlo1 + 1) * 8;
        for (int i = tid; i < n; i += 64) ((float4*)s1)[i] = ((const float4*)gb)[i];
        const float* gr = in1 + (size_t)b * 1024 + rhi1 * 32;
        if (tid < 32) s1[n * 4 + tid] = gr[tid];
    }
    {
        const float* gb = in2 + (size_t)b * 256 + rlo2 * 16;
        int n = (rhi2 - rlo2 + 1) * 4;
        for (int i = tid; i < n; i += 64) ((float4*)s2)[i] = ((const float4*)gb)[i];
        const float* gr = in2 + (size_t)b * 256 + rlo2 * 16 + (rhi2 - rlo2) * 16;
        if (tid < 16) s2[n * 4 + tid] = gr[tid];
    }

    const ull* bnd_other = isW0 ? bndW1 : bndW0;
    const ull w0p = pk2(W0, W0), w1p = pk2(W1, W1), w2p = pk2(W2, W2);

    S2<64> sA; S2<32> sB; S2<16> sC;
    ull haA = 0, hbA = 0, hcA = 0, hdA = 0;
    ull haB = 0, hbB = 0, hcB = 0, hdB = 0;
    float lmax = -INFINITY;
    float* mp = maps + (size_t)b * 65536 + (size_t)Y0 * 256 + cb;

    __syncthreads();

    // ---- prime rows h(Y0-2), h(Y0-1) (reflect at top edge) ----
    {
        int pr0 = (q == 0) ? 2 : Y0 - 2;
        int pr1 = (q == 0) ? 1 : Y0 - 1;
        s2_init(sA, s0, pr0, rlo0, cb);
        s2_init(sB, s1, pr0, rlo1, cb);
        s2_init(sC, s2, pr0, rlo2, cb);
        DO_ROW(0, false, false, false)
        s2_init(sA, s0, pr1, rlo0, cb);
        s2_init(sB, s1, pr1, rlo1, cb);
        s2_init(sC, s2, pr1, rlo2, cb);
        DO_ROW(1, false, false, false)
    }

    // ---- main strip ----
    s2_init(sA, s0, Y0, rlo0, cb);
    s2_init(sB, s1, Y0, rlo1, cb);
    s2_init(sC, s2, Y0, rlo2, cb);

    DO_ROW(0, true, false, true)     // row Y0
    DO_ROW(1, true, false, true)     // row Y0+1
    #pragma unroll 1
    for (int it = 0; it < 15; ++it) {
        DO_ROW(0, true, true, true)
        DO_ROW(1, true, true, true)
    }

    if (q < 7) {
        // rows Y0+32, Y0+33 finish v rows Y0+30, Y0+31 (no maps store)
        DO_ROW(0, false, true, true)
        DO_ROW(1, false, true, false)
    } else {
        // rings hold h252..h255; reflect rows 256->254, 257->253
        ull v254A = f2fma(w0p, f2add(haA, hcA),
                    f2fma(w1p, f2add(hbA, hdA), f2mul(w2p, hcA)));
        ull v255A = f2fma(w0p, f2add(hbA, hbA),
                    f2fma(w1p, f2add(hcA, hcA), f2mul(w2p, hdA)));
        ull v254B = f2fma(w0p, f2add(haB, hcB),
                    f2fma(w1p, f2add(hbB, hdB), f2mul(w2p, hcB)));
        ull v255B = f2fma(w0p, f2add(hbB, hbB),
                    f2fma(w1p, f2add(hcB, hcB), f2mul(w2p, hdB)));
        float2 a4 = up2(v254A), a5 = up2(v255A);
        float2 b4 = up2(v254B), b5 = up2(v255B);
        lmax = fmaxf(lmax, fmaxf(fmaxf(a4.x, a4.y), fmaxf(a5.x, a5.y)));
        lmax = fmaxf(lmax, fmaxf(fmaxf(b4.x, b4.y), fmaxf(b5.x, b5.y)));
    }

    // block max -> fused per-batch reduction (max is order-independent;
    // last-arriving block decodes and resets scratch for graph replay)
    #pragma unroll
    for (int off = 16; off; off >>= 1)
        lmax = fmaxf(lmax, __shfl_xor_sync(0xFFFFFFFFu, lmax, off));
    if (lane == 0) wred[tid >> 5] = lmax;
    __syncthreads();
    if (tid == 0) {
        float m = fmaxf(wred[0], wred[1]);
        atomicMax(&g_enc[b], enc_f(m));
        __threadfence();
        unsigned t = atomicAdd(&g_cnt[b], 1u);
        if (t == 7u) {
            unsigned e = atomicExch(&g_enc[b], 0u);
            scores[b] = dec_f(e);
            atomicExch(&g_cnt[b], 0u);
        }
    }
}

extern "C" void kernel_launch(void* const* d_in, const int* in_sizes, int n_in,
                              void* d_out, int out_size) {
    const float* out0 = (const float*)d_in[0];  // [256,64,64]
    const float* out1 = (const float*)d_in[1];  // [256,32,32]
    const float* out2 = (const float*)d_in[2];  // [256,16,16]
    float* out = (float*)d_out;

    fused_strip<<<2048, 64>>>(out0, out1, out2, out + 256, out);
}

// round 10
// speedup vs baseline: 1.0719x; 1.0719x over previous
#include <cuda_runtime.h>
#include <math.h>

// ---------------------------------------------------------------------------
// maps[b] = bilin_up(out0,64)+bilin_up(out1,32)+bilin_up(out2,16) -> 256x256
// scores[b] = max( reflect-pad 5x5 gaussian blur of maps[b] )
// d_out = [256 scores][256*256*256 maps] fp32.
//
// 1024 blocks = (batch, 64-row quarter strip), 128 threads = column pairs.
// R7 structure + center-tap-in-register h-blur: phase A keeps each row's own
// packed m in a register across the barrier, so phase B loads only the two
// neighbor pairs from smem (2 LDS.64 instead of 3). 4-row ring bounds the
// live m-registers. Incremental bilinear with packed fy (wrap recomputes
// brackets inline, uniform rare branch). Fused per-batch max via encoded
// atomicMax + arrival counter.
// ---------------------------------------------------------------------------

typedef unsigned long long ull;

#define W0 0.18762723f
#define W1 0.20606817f
#define W2 0.21260941f

__device__ __forceinline__ ull pk2(float a, float b) {
    ull r; asm("mov.b64 %0, {%1,%2};" : "=l"(r) : "f"(a), "f"(b)); return r;
}
__device__ __forceinline__ float2 up2(ull v) {
    float2 r; asm("mov.b64 {%0,%1}, %2;" : "=f"(r.x), "=f"(r.y) : "l"(v)); return r;
}
__device__ __forceinline__ ull f2add(ull a, ull b) {
    ull r; asm("add.rn.f32x2 %0,%1,%2;" : "=l"(r) : "l"(a), "l"(b)); return r;
}
__device__ __forceinline__ ull f2mul(ull a, ull b) {
    ull r; asm("mul.rn.f32x2 %0,%1,%2;" : "=l"(r) : "l"(a), "l"(b)); return r;
}
__device__ __forceinline__ ull f2fma(ull a, ull b, ull c) {
    ull r; asm("fma.rn.f32x2 %0,%1,%2,%3;" : "=l"(r) : "l"(a), "l"(b), "l"(c)); return r;
}

__device__ __forceinline__ unsigned enc_f(float f) {
    unsigned u = __float_as_uint(f);
    return (u & 0x80000000u) ? ~u : (u | 0x80000000u);
}
__device__ __forceinline__ float dec_f(unsigned u) {
    return (u & 0x80000000u) ? __uint_as_float(u & 0x7fffffffu)
                             : __uint_as_float(~u);
}

__device__ unsigned g_enc[256];   // zero-init; reset by last block each call
__device__ unsigned g_cnt[256];   // zero-init; reset by last block each call

// x-lerp of this thread's column pair from a staged source row
template<int H>
__device__ __forceinline__ float2 xlerp(const float* row, int tid) {
    int n0 = 2 * tid * (H - 1), n1 = n0 + (H - 1);
    int xa = n0 / 255, xb = n1 / 255;
    float fxa = (float)(n0 - 255 * xa) * (1.0f / 255.0f);
    float fxb = (float)(n1 - 255 * xb) * (1.0f / 255.0f);
    int xa1 = min(xa + 1, H - 1), xb1 = min(xb + 1, H - 1);
    float A = row[xa], B = row[xa1], C = row[xb], D = row[xb1];
    return make_float2(fmaf(fxa, B - A, A), fmaf(fxb, D - C, C));
}

template<int H>
struct SC {
    int rowoff;          // smem offset of source row y0
    ull fy2;             // packed (fy, fy)
    ull xlo2, xdf2;      // packed x-lerp at y0, packed (hi - lo)
};

template<int H>
__device__ __forceinline__ void sc_init(SC<H>& s, const float* sm, int y, int rlo, int tid) {
    int num = y * (H - 1);
    int y0 = num / 255;
    float fy = (float)(num - 255 * y0) * (1.0f / 255.0f);
    s.fy2 = pk2(fy, fy);
    s.rowoff = (y0 - rlo) * H;
    float2 lo = xlerp<H>(sm + s.rowoff, tid);
    float2 hi = xlerp<H>(sm + s.rowoff + H, tid);   // guard row keeps this defined
    s.xlo2 = pk2(lo.x, lo.y);
    s.xdf2 = pk2(hi.x - lo.x, hi.y - lo.y);
}

template<int H>
__device__ __forceinline__ ull sc_m(const SC<H>& s) {
    return f2fma(s.fy2, s.xdf2, s.xlo2);
}

template<int H>
__device__ __forceinline__ void sc_adv(SC<H>& s, const float* sm, ull inc2, ull m1_2, int tid) {
    s.fy2 = f2add(s.fy2, inc2);
    if (up2(s.fy2).x >= 1.0f) {       // uniform, rarely taken
        s.fy2 = f2add(s.fy2, m1_2);
        s.rowoff += H;
        s.xlo2 = f2add(s.xlo2, s.xdf2);            // new lo = old hi
        float2 hi = xlerp<H>(sm + s.rowoff + H, tid);
        float2 lo = up2(s.xlo2);
        s.xdf2 = pk2(hi.x - lo.x, hi.y - lo.y);
    }
}

// 5-tap h-blur: neighbors from smem (2 LDS.64), center tap from register
__device__ __forceinline__ ull hblur2(const float* row, ull p2,
                                      ull w0p, ull w1p, ull w2p) {
    ull p0 = *(const ull*)&row[0];   // (m-2, m-1)
    ull p4 = *(const ull*)&row[4];   // (m2,  m3)
    float2 a = up2(p0), b = up2(p2), c = up2(p4);
    ull p1 = pk2(a.y, b.x);
    ull p3 = pk2(b.y, c.x);
    return f2fma(w0p, f2add(p0, p4), f2fma(w1p, f2add(p1, p3), f2mul(w2p, p2)));
}

__global__ void __launch_bounds__(128, 7)
fused_quarter(const float* __restrict__ in0,
              const float* __restrict__ in1,
              const float* __restrict__ in2,
              float* __restrict__ maps,
              float* __restrict__ scores) {
    __shared__ __align__(16) float s0[20 * 64];   // staged + guard row
    __shared__ __align__(16) float s1[12 * 32];
    __shared__ __align__(16) float s2[8 * 16];
    __shared__ __align__(16) float mbuf[4][264];  // [0..259] used, pad 260..263
    __shared__ float wred[4];

    const int tid = threadIdx.x;
    const int bx  = blockIdx.x;
    const int b   = bx >> 2;
    const int q   = bx & 3;
    const int yq0 = q * 64;

    const int amin = max(0, yq0 - 2);
    const int amax = min(255, yq0 + 65);
    const int rlo0 = (amin * 63) / 255;
    const int rlo1 = (amin * 31) / 255;
    const int rlo2 = (amin * 15) / 255;
    const int rhi0 = min((amax * 63) / 255 + 1, 63);
    const int rhi1 = min((amax * 31) / 255 + 1, 31);
    const int rhi2 = min((amax * 15) / 255 + 1, 15);

    // stage sources (coalesced float4) + guard row (duplicate of last row)
    {
        const float* gb = in0 + (size_t)b * 4096 + rlo0 * 64;
        int n = (rhi0 - rlo0 + 1) * 16;
        for (int i = tid; i < n; i += 128) ((float4*)s0)[i] = ((const float4*)gb)[i];
        const float* gr = in0 + (size_t)b * 4096 + rhi0 * 64;
        if (tid < 64) s0[n * 4 + tid] = gr[tid];
    }
    {
        const float* gb = in1 + (size_t)b * 1024 + rlo1 * 32;
        int n = (rhi1 - rlo1 + 1) * 8;
        for (int i = tid; i < n; i += 128) ((float4*)s1)[i] = ((const float4*)gb)[i];
        const float* gr = in1 + (size_t)b * 1024 + rhi1 * 32;
        if (tid < 32) s1[n * 4 + tid] = gr[tid];
    }
    {
        const float* gb = in2 + (size_t)b * 256 + rlo2 * 16;
        int n = (rhi2 - rlo2 + 1) * 4;
        for (int i = tid; i < n; i += 128) ((float4*)s2)[i] = ((const float4*)gb)[i];
        const float* gr = in2 + (size_t)b * 256 + rhi2 * 16;
        if (tid < 16) s2[n * 4 + tid] = gr[tid];
    }

    // per-thread halo-store slot: threads 0/1/126/127 fill reflect cells,
    // everyone else hits the dummy pad (same-address stores collapse).
    int hoff; bool pickY;
    if (tid == 1)        { hoff = 0;   pickY = false; }
    else if (tid == 0)   { hoff = 1;   pickY = true;  }
    else if (tid == 127) { hoff = 258; pickY = false; }
    else if (tid == 126) { hoff = 259; pickY = true;  }
    else                 { hoff = 260; pickY = false; }

    const ull w0p = pk2(W0, W0), w1p = pk2(W1, W1), w2p = pk2(W2, W2);
    const ull incA = pk2(63.0f / 255.0f, 63.0f / 255.0f);
    const ull incB = pk2(31.0f / 255.0f, 31.0f / 255.0f);
    const ull incC = pk2(15.0f / 255.0f, 15.0f / 255.0f);
    const ull m1_2 = pk2(-1.0f, -1.0f);

    SC<64> cA; SC<32> cB; SC<16> cC;

    __syncthreads();

    // ---- prime rows h(yq0-2), h(yq0-1) (reflect at top edge) ----
    ull ha = 0, hb = 0, hc, hd;
    {
        int p0 = (q == 0) ? 2 : yq0 - 2;
        int p1 = (q == 0) ? 1 : yq0 - 1;
        sc_init(cA, s0, p0, rlo0, tid);
        sc_init(cB, s1, p0, rlo1, tid);
        sc_init(cC, s2, p0, rlo2, tid);
        ull m0 = f2add(f2add(sc_m(cA), sc_m(cB)), sc_m(cC));
        *(ull*)&mbuf[0][2 + 2 * tid] = m0;
        float2 mv = up2(m0);
        mbuf[0][hoff] = pickY ? mv.y : mv.x;
        sc_init(cA, s0, p1, rlo0, tid);
        sc_init(cB, s1, p1, rlo1, tid);
        sc_init(cC, s2, p1, rlo2, tid);
        ull m1 = f2add(f2add(sc_m(cA), sc_m(cB)), sc_m(cC));
        *(ull*)&mbuf[1][2 + 2 * tid] = m1;
        mv = up2(m1);
        mbuf[1][hoff] = pickY ? mv.y : mv.x;
        __syncthreads();
        hc = hblur2(&mbuf[0][2 * tid], m0, w0p, w1p, w2p);
        hd = hblur2(&mbuf[1][2 * tid], m1, w0p, w1p, w2p);
        __syncthreads();
    }

    // ---- main strip: 16 phases x 4 rows ----
    sc_init(cA, s0, yq0, rlo0, tid);
    sc_init(cB, s1, yq0, rlo1, tid);
    sc_init(cC, s2, yq0, rlo2, tid);

    float* mp = maps + (size_t)b * 65536 + (size_t)yq0 * 256 + 2 * tid;
    float lmax = -INFINITY;
    ull mr0, mr1, mr2, mr3;

#define PHASE_A(DOSTG)                                                   \
    {                                                                    \
        mr0 = f2add(f2add(sc_m(cA), sc_m(cB)), sc_m(cC));                \
        *(ull*)&mbuf[0][2 + 2 * tid] = mr0;                              \
        float2 mv = up2(mr0);                                            \
        mbuf[0][hoff] = pickY ? mv.y : mv.x;                             \
        if (DOSTG) *(ull*)(mp + 0 * 256) = mr0;                          \
        sc_adv(cA, s0, incA, m1_2, tid);                                 \
        sc_adv(cB, s1, incB, m1_2, tid);                                 \
        sc_adv(cC, s2, incC, m1_2, tid);                                 \
        mr1 = f2add(f2add(sc_m(cA), sc_m(cB)), sc_m(cC));                \
        *(ull*)&mbuf[1][2 + 2 * tid] = mr1;                              \
        mv = up2(mr1);                                                   \
        mbuf[1][hoff] = pickY ? mv.y : mv.x;                             \
        if (DOSTG) *(ull*)(mp + 1 * 256) = mr1;                          \
        sc_adv(cA, s0, incA, m1_2, tid);                                 \
        sc_adv(cB, s1, incB, m1_2, tid);                                 \
        sc_adv(cC, s2, incC, m1_2, tid);                                 \
        mr2 = f2add(f2add(sc_m(cA), sc_m(cB)), sc_m(cC));                \
        *(ull*)&mbuf[2][2 + 2 * tid] = mr2;                              \
        mv = up2(mr2);                                                   \
        mbuf[2][hoff] = pickY ? mv.y : mv.x;                             \
        if (DOSTG) *(ull*)(mp + 2 * 256) = mr2;                          \
        sc_adv(cA, s0, incA, m1_2, tid);                                 \
        sc_adv(cB, s1, incB, m1_2, tid);                                 \
        sc_adv(cC, s2, incC, m1_2, tid);                                 \
        mr3 = f2add(f2add(sc_m(cA), sc_m(cB)), sc_m(cC));                \
        *(ull*)&mbuf[3][2 + 2 * tid] = mr3;                              \
        mv = up2(mr3);                                                   \
        mbuf[3][hoff] = pickY ? mv.y : mv.x;                             \
        if (DOSTG) *(ull*)(mp + 3 * 256) = mr3;                          \
        sc_adv(cA, s0, incA, m1_2, tid);                                 \
        sc_adv(cB, s1, incB, m1_2, tid);                                 \
        sc_adv(cC, s2, incC, m1_2, tid);                                 \
    }

#define VROW(HE, DOMAX)                                                  \
    {                                                                    \
        ull he = (HE);                                                   \
        ull vv = f2fma(w0p, f2add(ha, he),                               \
                 f2fma(w1p, f2add(hb, hd), f2mul(w2p, hc)));             \
        if (DOMAX) {                                                     \
            float2 vf = up2(vv);                                         \
            lmax = fmaxf(lmax, fmaxf(vf.x, vf.y));                       \
        }                                                                \
        ha = hb; hb = hc; hc = hd; hd = he;                              \
    }

    // peeled phase 0 (first 2 v rows invalid)
    PHASE_A(true)
    mp += 1024;
    __syncthreads();
    VROW(hblur2(&mbuf[0][2 * tid], mr0, w0p, w1p, w2p), false)
    VROW(hblur2(&mbuf[1][2 * tid], mr1, w0p, w1p, w2p), false)
    VROW(hblur2(&mbuf[2][2 * tid], mr2, w0p, w1p, w2p), true)
    VROW(hblur2(&mbuf[3][2 * tid], mr3, w0p, w1p, w2p), true)
    __syncthreads();

    #pragma unroll 1
    for (int p = 1; p < 16; ++p) {
        PHASE_A(true)
        mp += 1024;
        __syncthreads();
        VROW(hblur2(&mbuf[0][2 * tid], mr0, w0p, w1p, w2p), true)
        VROW(hblur2(&mbuf[1][2 * tid], mr1, w0p, w1p, w2p), true)
        VROW(hblur2(&mbuf[2][2 * tid], mr2, w0p, w1p, w2p), true)
        VROW(hblur2(&mbuf[3][2 * tid], mr3, w0p, w1p, w2p), true)
        __syncthreads();
    }

    if (q < 3) {
        // rows yq0+64, yq0+65 finish v rows yq0+62, yq0+63 (no maps store)
        mr0 = f2add(f2add(sc_m(cA), sc_m(cB)), sc_m(cC));
        *(ull*)&mbuf[0][2 + 2 * tid] = mr0;
        float2 mv = up2(mr0);
        mbuf[0][hoff] = pickY ? mv.y : mv.x;
        sc_adv(cA, s0, incA, m1_2, tid);
        sc_adv(cB, s1, incB, m1_2, tid);
        sc_adv(cC, s2, incC, m1_2, tid);
        mr1 = f2add(f2add(sc_m(cA), sc_m(cB)), sc_m(cC));
        *(ull*)&mbuf[1][2 + 2 * tid] = mr1;
        mv = up2(mr1);
        mbuf[1][hoff] = pickY ? mv.y : mv.x;
        __syncthreads();
        VROW(hblur2(&mbuf[0][2 * tid], mr0, w0p, w1p, w2p), true)
        VROW(hblur2(&mbuf[1][2 * tid], mr1, w0p, w1p, w2p), true)
    } else {
        // ring holds h252..h255; reflect rows 256->254, 257->253
        ull v254 = f2fma(w0p, f2add(ha, hc), f2fma(w1p, f2add(hb, hd), f2mul(w2p, hc)));
        ull v255 = f2fma(w0p, f2add(hb, hb), f2fma(w1p, f2add(hc, hc), f2mul(w2p, hd)));
        float2 a4 = up2(v254), a5 = up2(v255);
        lmax = fmaxf(lmax, fmaxf(fmaxf(a4.x, a4.y), fmaxf(a5.x, a5.y)));
    }

    // block max -> fused per-batch reduction (max is order-independent;
    // last-arriving block decodes and resets scratch for graph replay)
    #pragma unroll
    for (int off = 16; off; off >>= 1)
        lmax = fmaxf(lmax, __shfl_xor_sync(0xFFFFFFFFu, lmax, off));
    if ((tid & 31) == 0) wred[tid >> 5] = lmax;
    __syncthreads();
    if (tid == 0) {
        float m = fmaxf(fmaxf(wred[0], wred[1]), fmaxf(wred[2], wred[3]));
        atomicMax(&g_enc[b], enc_f(m));
        __threadfence();
        unsigned t = atomicAdd(&g_cnt[b], 1u);
        if (t == 3u) {
            unsigned e = atomicExch(&g_enc[b], 0u);
            scores[b] = dec_f(e);
            atomicExch(&g_cnt[b], 0u);
        }
    }
}

extern "C" void kernel_launch(void* const* d_in, const int* in_sizes, int n_in,
                              void* d_out, int out_size) {
    const float* out0 = (const float*)d_in[0];  // [256,64,64]
    const float* out1 = (const float*)d_in[1];  // [256,32,32]
    const float* out2 = (const float*)d_in[2];  // [256,16,16]
    float* out = (float*)d_out;

    fused_quarter<<<1024, 128>>>(out0, out1, out2, out + 256, out);
}

// round 12
// speedup vs baseline: 1.1495x; 1.0724x over previous
#include <cuda_runtime.h>
#include <math.h>

// ---------------------------------------------------------------------------
// maps[b] = bilin_up(out0,64)+bilin_up(out1,32)+bilin_up(out2,16) -> 256x256
// scores[b] = max( reflect-pad 5x5 gaussian blur of maps[b] )
// d_out = [256 scores][256*256*256 maps] fp32.
//
// 1024 blocks = (batch, 64-row quarter strip), 128 threads = column pairs.
// R7 structure (known good) + ONE merged wrap branch per row for the 3 scale
// caches (bodies nested, warp-uniform). Packed-f32x2 fy tracking, x-lerp
// brackets recomputed only inside the wrap, guard row per staged scale,
// single-slot FSEL halo store, 8-row mbuf ring, register-ring v-blur.
// Fused per-batch max via encoded atomicMax + arrival counter.
// ---------------------------------------------------------------------------

typedef unsigned long long ull;

#define W0 0.18762723f
#define W1 0.20606817f
#define W2 0.21260941f

__device__ __forceinline__ ull pk2(float a, float b) {
    ull r; asm("mov.b64 %0, {%1,%2};" : "=l"(r) : "f"(a), "f"(b)); return r;
}
__device__ __forceinline__ float2 up2(ull v) {
    float2 r; asm("mov.b64 {%0,%1}, %2;" : "=f"(r.x), "=f"(r.y) : "l"(v)); return r;
}
__device__ __forceinline__ ull f2add(ull a, ull b) {
    ull r; asm("add.rn.f32x2 %0,%1,%2;" : "=l"(r) : "l"(a), "l"(b)); return r;
}
__device__ __forceinline__ ull f2mul(ull a, ull b) {
    ull r; asm("mul.rn.f32x2 %0,%1,%2;" : "=l"(r) : "l"(a), "l"(b)); return r;
}
__device__ __forceinline__ ull f2fma(ull a, ull b, ull c) {
    ull r; asm("fma.rn.f32x2 %0,%1,%2,%3;" : "=l"(r) : "l"(a), "l"(b), "l"(c)); return r;
}

__device__ __forceinline__ unsigned enc_f(float f) {
    unsigned u = __float_as_uint(f);
    return (u & 0x80000000u) ? ~u : (u | 0x80000000u);
}
__device__ __forceinline__ float dec_f(unsigned u) {
    return (u & 0x80000000u) ? __uint_as_float(u & 0x7fffffffu)
                             : __uint_as_float(~u);
}

__device__ unsigned g_enc[256];   // zero-init; reset by last block each call
__device__ unsigned g_cnt[256];   // zero-init; reset by last block each call

// x-lerp of this thread's column pair from a staged source row
template<int H>
__device__ __forceinline__ float2 xlerp(const float* row, int tid) {
    int n0 = 2 * tid * (H - 1), n1 = n0 + (H - 1);
    int xa = n0 / 255, xb = n1 / 255;
    float fxa = (float)(n0 - 255 * xa) * (1.0f / 255.0f);
    float fxb = (float)(n1 - 255 * xb) * (1.0f / 255.0f);
    int xa1 = min(xa + 1, H - 1), xb1 = min(xb + 1, H - 1);
    float A = row[xa], B = row[xa1], C = row[xb], D = row[xb1];
    return make_float2(fmaf(fxa, B - A, A), fmaf(fxb, D - C, C));
}

template<int H>
struct SC {
    int rowoff;          // smem offset of source row y0
    ull fy2;             // packed (fy, fy)
    ull xlo2, xdf2;      // packed x-lerp at y0, packed (hi - lo)
};

template<int H>
__device__ __forceinline__ void sc_init(SC<H>& s, const float* sm, int y, int rlo, int tid) {
    int num = y * (H - 1);
    int y0 = num / 255;
    float fy = (float)(num - 255 * y0) * (1.0f / 255.0f);
    s.fy2 = pk2(fy, fy);
    s.rowoff = (y0 - rlo) * H;
    float2 lo = xlerp<H>(sm + s.rowoff, tid);
    float2 hi = xlerp<H>(sm + s.rowoff + H, tid);   // guard row keeps this defined
    s.xlo2 = pk2(lo.x, lo.y);
    s.xdf2 = pk2(hi.x - lo.x, hi.y - lo.y);
}

template<int H>
__device__ __forceinline__ ull sc_m(const SC<H>& s) {
    return f2fma(s.fy2, s.xdf2, s.xlo2);
}

template<int H>
__device__ __forceinline__ void sc_wrap(SC<H>& s, const float* sm, ull m1_2, int tid) {
    s.fy2 = f2add(s.fy2, m1_2);
    s.rowoff += H;
    s.xlo2 = f2add(s.xlo2, s.xdf2);            // new lo = old hi
    float2 hi = xlerp<H>(sm + s.rowoff + H, tid);
    float2 lo = up2(s.xlo2);
    s.xdf2 = pk2(hi.x - lo.x, hi.y - lo.y);
}

// packed 5-tap horizontal blur; row = &mbuf[r][2*tid] (8B aligned)
__device__ __forceinline__ ull hblur(const float* row, ull w0p, ull w1p, ull w2p) {
    ull p0 = *(const ull*)&row[0];   // (m-2, m-1)
    ull p2 = *(const ull*)&row[2];   // (m0,  m1)
    ull p4 = *(const ull*)&row[4];   // (m2,  m3)
    float2 a = up2(p0), b = up2(p2), c = up2(p4);
    ull p1 = pk2(a.y, b.x);
    ull p3 = pk2(b.y, c.x);
    return f2fma(w0p, f2add(p0, p4), f2fma(w1p, f2add(p1, p3), f2mul(w2p, p2)));
}

__global__ void __launch_bounds__(128, 7)
fused_quarter(const float* __restrict__ in0,
              const float* __restrict__ in1,
              const float* __restrict__ in2,
              float* __restrict__ maps,
              float* __restrict__ scores) {
    __shared__ __align__(16) float s0[20 * 64];   // staged + guard row
    __shared__ __align__(16) float s1[12 * 32];
    __shared__ __align__(16) float s2[8 * 16];
    __shared__ __align__(16) float mbuf[8][264];  // [0..259] used, pad 260..263
    __shared__ float wred[4];

    const int tid = threadIdx.x;
    const int bx  = blockIdx.x;
    const int b   = bx >> 2;
    const int q   = bx & 3;
    const int yq0 = q * 64;

    const int amin = max(0, yq0 - 2);
    const int amax = min(255, yq0 + 65);
    const int rlo0 = (amin * 63) / 255;
    const int rlo1 = (amin * 31) / 255;
    const int rlo2 = (amin * 15) / 255;
    const int rhi0 = min((amax * 63) / 255 + 1, 63);
    const int rhi1 = min((amax * 31) / 255 + 1, 31);
    const int rhi2 = min((amax * 15) / 255 + 1, 15);

    // stage sources (coalesced float4) + guard row (duplicate of last row)
    {
        const float* gb = in0 + (size_t)b * 4096 + rlo0 * 64;
        int n = (rhi0 - rlo0 + 1) * 16;
        for (int i = tid; i < n; i += 128) ((float4*)s0)[i] = ((const float4*)gb)[i];
        const float* gr = in0 + (size_t)b * 4096 + rhi0 * 64;
        if (tid < 64) s0[n * 4 + tid] = gr[tid];
    }
    {
        const float* gb = in1 + (size_t)b * 1024 + rlo1 * 32;
        int n = (rhi1 - rlo1 + 1) * 8;
        for (int i = tid; i < n; i += 128) ((float4*)s1)[i] = ((const float4*)gb)[i];
        const float* gr = in1 + (size_t)b * 1024 + rhi1 * 32;
        if (tid < 32) s1[n * 4 + tid] = gr[tid];
    }
    {
        const float* gb = in2 + (size_t)b * 256 + rlo2 * 16;
        int n = (rhi2 - rlo2 + 1) * 4;
        for (int i = tid; i < n; i += 128) ((float4*)s2)[i] = ((const float4*)gb)[i];
        const float* gr = in2 + (size_t)b * 256 + rhi2 * 16;
        if (tid < 16) s2[n * 4 + tid] = gr[tid];
    }

    // per-thread halo-store slot: threads 0/1/126/127 fill reflect cells,
    // everyone else hits the dummy pad (same-address stores collapse).
    int hoff; bool pickY;
    if (tid == 1)        { hoff = 0;   pickY = false; }
    else if (tid == 0)   { hoff = 1;   pickY = true;  }
    else if (tid == 127) { hoff = 258; pickY = false; }
    else if (tid == 126) { hoff = 259; pickY = true;  }
    else                 { hoff = 260; pickY = false; }

    const ull w0p = pk2(W0, W0), w1p = pk2(W1, W1), w2p = pk2(W2, W2);
    const ull incA = pk2(63.0f / 255.0f, 63.0f / 255.0f);
    const ull incB = pk2(31.0f / 255.0f, 31.0f / 255.0f);
    const ull incC = pk2(15.0f / 255.0f, 15.0f / 255.0f);
    const ull m1_2 = pk2(-1.0f, -1.0f);

    SC<64> cA; SC<32> cB; SC<16> cC;

    __syncthreads();

// merged advance: ONE uniform branch per row for all 3 scales
#define ADV_ALL                                                          \
    {                                                                    \
        cA.fy2 = f2add(cA.fy2, incA);                                    \
        cB.fy2 = f2add(cB.fy2, incB);                                    \
        cC.fy2 = f2add(cC.fy2, incC);                                    \
        bool wA = up2(cA.fy2).x >= 1.0f;                                 \
        bool wB = up2(cB.fy2).x >= 1.0f;                                 \
        bool wC = up2(cC.fy2).x >= 1.0f;                                 \
        if (wA | wB | wC) {                                              \
            if (wA) sc_wrap(cA, s0, m1_2, tid);                          \
            if (wB) sc_wrap(cB, s1, m1_2, tid);                          \
            if (wC) sc_wrap(cC, s2, m1_2, tid);                          \
        }                                                                \
    }

    // ---- prime rows h(yq0-2), h(yq0-1) (reflect at top edge) ----
    {
        int p0 = (q == 0) ? 2 : yq0 - 2;
        int p1 = (q == 0) ? 1 : yq0 - 1;
        sc_init(cA, s0, p0, rlo0, tid);
        sc_init(cB, s1, p0, rlo1, tid);
        sc_init(cC, s2, p0, rlo2, tid);
        ull m2 = f2add(f2add(sc_m(cA), sc_m(cB)), sc_m(cC));
        *(ull*)&mbuf[0][2 + 2 * tid] = m2;
        float2 mv = up2(m2);
        mbuf[0][hoff] = pickY ? mv.y : mv.x;
        sc_init(cA, s0, p1, rlo0, tid);
        sc_init(cB, s1, p1, rlo1, tid);
        sc_init(cC, s2, p1, rlo2, tid);
        m2 = f2add(f2add(sc_m(cA), sc_m(cB)), sc_m(cC));
        *(ull*)&mbuf[1][2 + 2 * tid] = m2;
        mv = up2(m2);
        mbuf[1][hoff] = pickY ? mv.y : mv.x;
    }
    __syncthreads();
    ull ha = 0, hb = 0;
    ull hc = hblur(&mbuf[0][2 * tid], w0p, w1p, w2p);
    ull hd = hblur(&mbuf[1][2 * tid], w0p, w1p, w2p);
    __syncthreads();

    // ---- main strip: 8 phases x 8 rows ----
    sc_init(cA, s0, yq0, rlo0, tid);
    sc_init(cB, s1, yq0, rlo1, tid);
    sc_init(cC, s2, yq0, rlo2, tid);

    float* mp = maps + (size_t)b * 65536 + (size_t)yq0 * 256 + 2 * tid;
    float lmax = -INFINITY;

    // peeled phase 0 (max-guard only here)
    {
        #pragma unroll
        for (int r = 0; r < 8; ++r) {
            ull m2 = f2add(f2add(sc_m(cA), sc_m(cB)), sc_m(cC));
            *(ull*)&mbuf[r][2 + 2 * tid] = m2;
            float2 mv = up2(m2);
            mbuf[r][hoff] = pickY ? mv.y : mv.x;
            *(ull*)(mp + r * 256) = m2;
            ADV_ALL
        }
        mp += 2048;
        __syncthreads();
        #pragma unroll
        for (int r = 0; r < 8; ++r) {
            ull he = hblur(&mbuf[r][2 * tid], w0p, w1p, w2p);
            ull vv = f2fma(w0p, f2add(ha, he),
                     f2fma(w1p, f2add(hb, hd), f2mul(w2p, hc)));
            if (r >= 2) {
                float2 vf = up2(vv);
                lmax = fmaxf(lmax, fmaxf(vf.x, vf.y));
            }
            ha = hb; hb = hc; hc = hd; hd = he;
        }
        __syncthreads();
    }

    #pragma unroll 1
    for (int p = 1; p < 8; ++p) {
        #pragma unroll
        for (int r = 0; r < 8; ++r) {
            ull m2 = f2add(f2add(sc_m(cA), sc_m(cB)), sc_m(cC));
            *(ull*)&mbuf[r][2 + 2 * tid] = m2;
            float2 mv = up2(m2);
            mbuf[r][hoff] = pickY ? mv.y : mv.x;
            *(ull*)(mp + r * 256) = m2;
            ADV_ALL
        }
        mp += 2048;
        __syncthreads();
        #pragma unroll
        for (int r = 0; r < 8; ++r) {
            ull he = hblur(&mbuf[r][2 * tid], w0p, w1p, w2p);
            ull vv = f2fma(w0p, f2add(ha, he),
                     f2fma(w1p, f2add(hb, hd), f2mul(w2p, hc)));
            float2 vf = up2(vv);
            lmax = fmaxf(lmax, fmaxf(vf.x, vf.y));
            ha = hb; hb = hc; hc = hd; hd = he;
        }
        __syncthreads();
    }

    if (q < 3) {
        // rows yq0+64, yq0+65 finish v rows yq0+62, yq0+63 (no maps store)
        #pragma unroll
        for (int e = 0; e < 2; ++e) {
            ull m2 = f2add(f2add(sc_m(cA), sc_m(cB)), sc_m(cC));
            *(ull*)&mbuf[e][2 + 2 * tid] = m2;
            float2 mv = up2(m2);
            mbuf[e][hoff] = pickY ? mv.y : mv.x;
            ADV_ALL
        }
        __syncthreads();
        #pragma unroll
        for (int e = 0; e < 2; ++e) {
            ull he = hblur(&mbuf[e][2 * tid], w0p, w1p, w2p);
            ull vv = f2fma(w0p, f2add(ha, he),
                     f2fma(w1p, f2add(hb, hd), f2mul(w2p, hc)));
            float2 vf = up2(vv);
            lmax = fmaxf(lmax, fmaxf(vf.x, vf.y));
            ha = hb; hb = hc; hc = hd; hd = he;
        }
    } else {
        // ring holds h252..h255; reflect rows 256->254, 257->253
        ull v254 = f2fma(w0p, f2add(ha, hc), f2fma(w1p, f2add(hb, hd), f2mul(w2p, hc)));
        ull v255 = f2fma(w0p, f2add(hb, hb), f2fma(w1p, f2add(hc, hc), f2mul(w2p, hd)));
        float2 a4 = up2(v254), a5 = up2(v255);
        lmax = fmaxf(lmax, fmaxf(fmaxf(a4.x, a4.y), fmaxf(a5.x, a5.y)));
    }

    // block max -> fused per-batch reduction (max is order-independent;
    // last-arriving block decodes and resets scratch for graph replay)
    #pragma unroll
    for (int off = 16; off; off >>= 1)
        lmax = fmaxf(lmax, __shfl_xor_sync(0xFFFFFFFFu, lmax, off));
    if ((tid & 31) == 0) wred[tid >> 5] = lmax;
    __syncthreads();
    if (tid == 0) {
        float m = fmaxf(fmaxf(wred[0], wred[1]), fmaxf(wred[2], wred[3]));
        atomicMax(&g_enc[b], enc_f(m));
        __threadfence();
        unsigned t = atomicAdd(&g_cnt[b], 1u);
        if (t == 3u) {
            unsigned e = atomicExch(&g_enc[b], 0u);
            scores[b] = dec_f(e);
            atomicExch(&g_cnt[b], 0u);
        }
    }
}

extern "C" void kernel_launch(void* const* d_in, const int* in_sizes, int n_in,
                              void* d_out, int out_size) {
    const float* out0 = (const float*)d_in[0];  // [256,64,64]
    const float* out1 = (const float*)d_in[1];  // [256,32,32]
    const float* out2 = (const float*)d_in[2];  // [256,16,16]
    float* out = (float*)d_out;

    fused_quarter<<<1024, 128>>>(out0, out1, out2, out + 256, out);
}